// round 1
// baseline (speedup 1.0000x reference)
#include <cuda_runtime.h>
#include <math.h>
#include <float.h>

// Problem constants (shapes are fixed by the dataset).
#define NN 100000
#define EE 1600000
#define HH 64
#define CC 10

// ---------------- static device scratch (no allocations allowed) ----------------
__device__ int   g_src[EE];
__device__ int   g_dst[EE];
__device__ int   g_col[EE];          // CSR column (src) indices grouped by dst
__device__ int   g_deg[NN];
__device__ int   g_rowptr[NN + 1];
__device__ int   g_cursor[NN];
__device__ float g_h[NN * HH];       // node features (updated in place)
__device__ float g_agg[NN * HH];     // segment-max result
__device__ int   g_odd_nonzero;      // edge dtype detection flag

// ---------------- setup kernels ----------------
__global__ void zero_kernel() {
    int i = blockIdx.x * blockDim.x + threadIdx.x;
    if (i < NN) g_deg[i] = 0;
    if (i == 0) g_odd_nonzero = 0;
}

// Detect whether edge_index is int64 or int32.
// Node ids < 100000 < 2^31, so for int64 (little-endian) every odd 32-bit word
// is 0. For int32, odd words are node ids (P(zero) = 1e-5 each).
__global__ void detect_kernel(const unsigned int* __restrict__ w) {
    int i = blockIdx.x * blockDim.x + threadIdx.x;   // 65536 threads
    unsigned int v = w[2 * i + 1];                   // max idx 131071 < 2*EE words
    if (v) atomicOr(&g_odd_nonzero, 1);
}

// Convert edges to int32 src/dst arrays and count in-degrees.
__global__ void convert_kernel(const void* __restrict__ ei) {
    int i = blockIdx.x * blockDim.x + threadIdx.x;
    if (i >= EE) return;
    int s, d;
    if (g_odd_nonzero == 0) {
        const long long* p = (const long long*)ei;
        s = (int)p[i];
        d = (int)p[EE + i];
    } else {
        const int* p = (const int*)ei;
        s = p[i];
        d = p[EE + i];
    }
    g_src[i] = s;
    g_dst[i] = d;
    atomicAdd(&g_deg[d], 1);
}

// Single-block exclusive scan of degrees -> rowptr (+ cursor copy).
__global__ void scan_kernel() {
    __shared__ int sm[1024];
    __shared__ int carry;
    int tid = threadIdx.x;
    if (tid == 0) carry = 0;
    __syncthreads();
    for (int base = 0; base < NN; base += 1024) {
        int i = base + tid;
        int v = (i < NN) ? g_deg[i] : 0;
        sm[tid] = v;
        __syncthreads();
        for (int off = 1; off < 1024; off <<= 1) {
            int t = (tid >= off) ? sm[tid - off] : 0;
            __syncthreads();
            sm[tid] += t;
            __syncthreads();
        }
        int excl = sm[tid] - v + carry;
        if (i < NN) { g_rowptr[i] = excl; g_cursor[i] = excl; }
        __syncthreads();
        if (tid == 1023) carry += sm[1023];
        __syncthreads();
    }
    if (tid == 0) g_rowptr[NN] = carry;
}

__global__ void scatter_kernel() {
    int i = blockIdx.x * blockDim.x + threadIdx.x;
    if (i >= EE) return;
    int d = g_dst[i];
    int pos = atomicAdd(&g_cursor[d], 1);
    g_col[pos] = g_src[i];
}

// ---------------- segment max: one warp per destination node ----------------
// Each lane owns 2 features (float2) of the 64-float row -> 256B coalesced
// load per edge. Columns staged through a lane register + shfl so the warp
// issues independent gather loads (MLP up to 32).
__global__ void segmax_kernel() {
    int gw   = (blockIdx.x * blockDim.x + threadIdx.x) >> 5;
    int lane = threadIdx.x & 31;
    if (gw >= NN) return;
    int beg = g_rowptr[gw], end = g_rowptr[gw + 1];
    float m0 = -FLT_MAX, m1 = -FLT_MAX;
    for (int base = beg; base < end; base += 32) {
        int cnt = min(32, end - base);
        int s = 0;
        if (lane < cnt) s = g_col[base + lane];
        for (int e = 0; e < cnt; e++) {
            int sv = __shfl_sync(0xffffffffu, s, e);
            float2 v = *(const float2*)(g_h + sv * HH + lane * 2);
            m0 = fmaxf(m0, v.x);
            m1 = fmaxf(m1, v.y);
        }
    }
    if (beg == end) { m0 = 0.f; m1 = 0.f; }  // empty segment -> 0 (isfinite rule)
    ((float2*)g_agg)[gw * 32 + lane] = make_float2(m0, m1);
}

// ---------------- 64-wide GEMM: C = (A [+ A2]) @ W + b ----------------
// 64 rows x 64 cols per block, 256 threads, 4x4 microtile. In-place safe:
// a block stages its own rows to smem before writing the same rows.
template <bool ADD>
__global__ void gemm64_kernel(const float* __restrict__ A,
                              const float* __restrict__ A2,
                              const float* __restrict__ W,
                              const float* __restrict__ bias,
                              float* __restrict__ Cm, int n) {
    __shared__ float As[64][68];
    __shared__ float Ws[64][68];
    int tid = threadIdx.x;
    int block_row = blockIdx.x * 64;

    for (int i = tid; i < 1024; i += 256) {           // W: [k][j] row-major
        int k = i >> 4, j4 = i & 15;
        float4 v = ((const float4*)W)[i];
        *(float4*)&Ws[k][j4 * 4] = v;
    }
    for (int i = tid; i < 1024; i += 256) {           // A rows (+agg)
        int m = i >> 4, k4 = i & 15;
        int row = block_row + m;
        float4 v = make_float4(0.f, 0.f, 0.f, 0.f);
        if (row < n) {
            v = ((const float4*)A)[row * 16 + k4];
            if (ADD) {
                float4 u = ((const float4*)A2)[row * 16 + k4];
                v.x += u.x; v.y += u.y; v.z += u.z; v.w += u.w;
            }
        }
        *(float4*)&As[m][k4 * 4] = v;
    }
    __syncthreads();

    int tx = tid & 15, ty = tid >> 4;
    int m0 = ty * 4, j0 = tx * 4;
    float acc[4][4];
#pragma unroll
    for (int i = 0; i < 4; i++)
#pragma unroll
        for (int j = 0; j < 4; j++) acc[i][j] = 0.f;

#pragma unroll 16
    for (int k = 0; k < 64; k++) {
        float b0 = Ws[k][j0], b1 = Ws[k][j0 + 1], b2 = Ws[k][j0 + 2], b3 = Ws[k][j0 + 3];
#pragma unroll
        for (int i = 0; i < 4; i++) {
            float a = As[m0 + i][k];
            acc[i][0] = fmaf(a, b0, acc[i][0]);
            acc[i][1] = fmaf(a, b1, acc[i][1]);
            acc[i][2] = fmaf(a, b2, acc[i][2]);
            acc[i][3] = fmaf(a, b3, acc[i][3]);
        }
    }
    float bb0 = bias[j0], bb1 = bias[j0 + 1], bb2 = bias[j0 + 2], bb3 = bias[j0 + 3];
#pragma unroll
    for (int i = 0; i < 4; i++) {
        int row = block_row + m0 + i;
        if (row < n) {
            float4 o = make_float4(acc[i][0] + bb0, acc[i][1] + bb1,
                                   acc[i][2] + bb2, acc[i][3] + bb3);
            ((float4*)Cm)[row * 16 + (j0 >> 2)] = o;
        }
    }
}

// ---------------- decoder + log-softmax: one thread per node ----------------
__global__ void decoder_kernel(const float* __restrict__ dw,
                               const float* __restrict__ db,
                               float* __restrict__ out, int n) {
    __shared__ float Ws[HH * CC];
    __shared__ float bs[CC];
    int tid = threadIdx.x;
    for (int i = tid; i < HH * CC; i += blockDim.x) Ws[i] = dw[i];
    if (tid < CC) bs[tid] = db[tid];
    __syncthreads();
    int node = blockIdx.x * blockDim.x + tid;
    if (node >= n) return;
    float acc[CC];
#pragma unroll
    for (int c = 0; c < CC; c++) acc[c] = bs[c];
    const float4* hp = (const float4*)(g_h + node * HH);
#pragma unroll
    for (int k4 = 0; k4 < 16; k4++) {
        float4 v = hp[k4];
        int kb = k4 * 4;
#pragma unroll
        for (int c = 0; c < CC; c++)
            acc[c] += v.x * Ws[(kb + 0) * CC + c] + v.y * Ws[(kb + 1) * CC + c] +
                      v.z * Ws[(kb + 2) * CC + c] + v.w * Ws[(kb + 3) * CC + c];
    }
    float mx = acc[0];
#pragma unroll
    for (int c = 1; c < CC; c++) mx = fmaxf(mx, acc[c]);
    float s = 0.f;
#pragma unroll
    for (int c = 0; c < CC; c++) s += expf(acc[c] - mx);
    float lse = mx + logf(s);
#pragma unroll
    for (int c = 0; c < CC; c++) out[node * CC + c] = acc[c] - lse;
}

// ---------------- launch ----------------
extern "C" void kernel_launch(void* const* d_in, const int* in_sizes, int n_in,
                              void* d_out, int out_size) {
    const float* x      = (const float*)d_in[0];
    const void*  ei     = d_in[1];
    // d_in[2] = diameter (constant 6 for this problem; loop is unrolled into
    // the graph since a data-dependent host loop is not graph-capturable)
    const float* enc_w  = (const float*)d_in[3];
    const float* enc_b  = (const float*)d_in[4];
    const float* proc_w = (const float*)d_in[5];
    const float* proc_b = (const float*)d_in[6];
    const float* dec_w  = (const float*)d_in[7];
    const float* dec_b  = (const float*)d_in[8];
    float* out = (float*)d_out;

    float* hptr = nullptr;
    float* aggptr = nullptr;
    cudaGetSymbolAddress((void**)&hptr, g_h);
    cudaGetSymbolAddress((void**)&aggptr, g_agg);

    const int n = NN;

    // CSR build (runs every replay; ~20us)
    zero_kernel<<<(NN + 255) / 256, 256>>>();
    detect_kernel<<<256, 256>>>((const unsigned int*)ei);
    convert_kernel<<<(EE + 255) / 256, 256>>>(ei);
    scan_kernel<<<1, 1024>>>();
    scatter_kernel<<<(EE + 255) / 256, 256>>>();

    // encoder
    gemm64_kernel<false><<<(n + 63) / 64, 256>>>(x, nullptr, enc_w, enc_b, hptr, n);

    // 6 GIN layers
    for (int it = 0; it < 6; it++) {
        segmax_kernel<<<(NN * 32 + 255) / 256, 256>>>();
        gemm64_kernel<true><<<(n + 63) / 64, 256>>>(hptr, aggptr, proc_w, proc_b, hptr, n);
    }

    // decoder + log-softmax
    decoder_kernel<<<(n + 127) / 128, 128>>>(dec_w, dec_b, out, n);
}

// round 2
// speedup vs baseline: 1.2965x; 1.2965x over previous
#include <cuda_runtime.h>
#include <math.h>
#include <float.h>

#define NN 100000
#define EE 1600000
#define HH 64
#define CC 10
#define SCAN_BLK 1024
#define SCAN_NBLK ((NN + SCAN_BLK - 1) / SCAN_BLK)   // 98

// ---------------- static device scratch ----------------
__device__ int   g_src[EE];
__device__ int   g_dst[EE];
__device__ int   g_col[EE];
__device__ int   g_deg[NN];
__device__ int   g_rowptr[NN + 1];
__device__ int   g_cursor[NN];
__device__ int   g_blocksum[SCAN_NBLK];
__device__ float g_h[NN * HH];
__device__ float g_agg[NN * HH];
__device__ int   g_odd_nonzero;

// ---------------- setup ----------------
__global__ void zero_kernel() {
    int i = blockIdx.x * blockDim.x + threadIdx.x;
    if (i < NN) g_deg[i] = 0;
    if (i == 0) g_odd_nonzero = 0;
}

// int64-vs-int32 edge dtype detection (node ids < 2^31 -> int64 odd words are 0).
__global__ void detect_kernel(const unsigned int* __restrict__ w) {
    int i = blockIdx.x * blockDim.x + threadIdx.x;   // 65536 threads
    unsigned int v = w[2 * i + 1];
    if (v) atomicOr(&g_odd_nonzero, 1);
}

__global__ void convert_kernel(const void* __restrict__ ei) {
    int i = blockIdx.x * blockDim.x + threadIdx.x;
    if (i >= EE) return;
    int s, d;
    if (g_odd_nonzero == 0) {
        const long long* p = (const long long*)ei;
        s = (int)p[i];
        d = (int)p[EE + i];
    } else {
        const int* p = (const int*)ei;
        s = p[i];
        d = p[EE + i];
    }
    g_src[i] = s;
    g_dst[i] = d;
    atomicAdd(&g_deg[d], 1);
}

// ---------------- multi-block exclusive scan ----------------
// Phase 1: per-block exclusive scan of deg -> rowptr (block-local), block sum out.
__global__ void scan_phase1() {
    __shared__ int warp_sums[32];
    int tid = threadIdx.x;
    int i = blockIdx.x * SCAN_BLK + tid;
    int v = (i < NN) ? g_deg[i] : 0;
    int lane = tid & 31, wid = tid >> 5;

    // warp inclusive scan
    int incl = v;
#pragma unroll
    for (int off = 1; off < 32; off <<= 1) {
        int t = __shfl_up_sync(0xffffffffu, incl, off);
        if (lane >= off) incl += t;
    }
    if (lane == 31) warp_sums[wid] = incl;
    __syncthreads();
    if (wid == 0) {
        int ws = (lane < 32) ? warp_sums[lane] : 0;
        int wincl = ws;
#pragma unroll
        for (int off = 1; off < 32; off <<= 1) {
            int t = __shfl_up_sync(0xffffffffu, wincl, off);
            if (lane >= off) wincl += t;
        }
        warp_sums[lane] = wincl - ws;   // exclusive warp offsets
        if (lane == 31) g_blocksum[blockIdx.x] = wincl;
    }
    __syncthreads();
    int excl = incl - v + warp_sums[wid];
    if (i < NN) g_rowptr[i] = excl;
}

// Phase 2: single small block scans the 98 block sums (exclusive, in place).
__global__ void scan_phase2() {
    __shared__ int sm[SCAN_NBLK];
    int tid = threadIdx.x;            // 128 threads
    int v = (tid < SCAN_NBLK) ? g_blocksum[tid] : 0;
    int lane = tid & 31, wid = tid >> 5;
    __shared__ int ws4[4];
    int incl = v;
#pragma unroll
    for (int off = 1; off < 32; off <<= 1) {
        int t = __shfl_up_sync(0xffffffffu, incl, off);
        if (lane >= off) incl += t;
    }
    if (lane == 31) ws4[wid] = incl;
    __syncthreads();
    if (tid == 0) {
        int c = 0;
        for (int w = 0; w < 4; w++) { int t = ws4[w]; ws4[w] = c; c += t; }
        sm[0] = c;                    // total edge count
    }
    __syncthreads();
    if (tid < SCAN_NBLK) g_blocksum[tid] = incl - v + ws4[wid];
    if (tid == 0) g_rowptr[NN] = sm[0];
}

// Phase 3: add block offsets; produce final rowptr + cursor.
__global__ void scan_phase3() {
    int i = blockIdx.x * SCAN_BLK + threadIdx.x;
    if (i >= NN) return;
    int r = g_rowptr[i] + g_blocksum[blockIdx.x];
    g_rowptr[i] = r;
    g_cursor[i] = r;
}

__global__ void scatter_kernel() {
    int i = blockIdx.x * blockDim.x + threadIdx.x;
    if (i >= EE) return;
    int d = g_dst[i];
    int pos = atomicAdd(&g_cursor[d], 1);
    g_col[pos] = g_src[i];
}

// ---------------- segment max: one warp per destination node ----------------
__global__ void segmax_kernel() {
    int gw   = (blockIdx.x * blockDim.x + threadIdx.x) >> 5;
    int lane = threadIdx.x & 31;
    if (gw >= NN) return;
    int beg = g_rowptr[gw], end = g_rowptr[gw + 1];
    float m0 = -FLT_MAX, m1 = -FLT_MAX;
    for (int base = beg; base < end; base += 32) {
        int cnt = min(32, end - base);
        int s = 0;
        if (lane < cnt) s = g_col[base + lane];
        for (int e = 0; e < cnt; e++) {
            int sv = __shfl_sync(0xffffffffu, s, e);
            float2 v = *(const float2*)(g_h + sv * HH + lane * 2);
            m0 = fmaxf(m0, v.x);
            m1 = fmaxf(m1, v.y);
        }
    }
    if (beg == end) { m0 = 0.f; m1 = 0.f; }
    ((float2*)g_agg)[gw * 32 + lane] = make_float2(m0, m1);
}

// ---------------- 64-wide GEMM: C = (A [+ A2]) @ W + b ----------------
template <bool ADD>
__global__ void gemm64_kernel(const float* __restrict__ A,
                              const float* __restrict__ A2,
                              const float* __restrict__ W,
                              const float* __restrict__ bias,
                              float* __restrict__ Cm, int n) {
    __shared__ float As[64][68];
    __shared__ float Ws[64][68];
    int tid = threadIdx.x;
    int block_row = blockIdx.x * 64;

    for (int i = tid; i < 1024; i += 256) {
        int k = i >> 4, j4 = i & 15;
        float4 v = ((const float4*)W)[i];
        *(float4*)&Ws[k][j4 * 4] = v;
    }
    for (int i = tid; i < 1024; i += 256) {
        int m = i >> 4, k4 = i & 15;
        int row = block_row + m;
        float4 v = make_float4(0.f, 0.f, 0.f, 0.f);
        if (row < n) {
            v = ((const float4*)A)[row * 16 + k4];
            if (ADD) {
                float4 u = ((const float4*)A2)[row * 16 + k4];
                v.x += u.x; v.y += u.y; v.z += u.z; v.w += u.w;
            }
        }
        *(float4*)&As[m][k4 * 4] = v;
    }
    __syncthreads();

    int tx = tid & 15, ty = tid >> 4;
    int m0 = ty * 4, j0 = tx * 4;
    float acc[4][4];
#pragma unroll
    for (int i = 0; i < 4; i++)
#pragma unroll
        for (int j = 0; j < 4; j++) acc[i][j] = 0.f;

#pragma unroll 16
    for (int k = 0; k < 64; k++) {
        float b0 = Ws[k][j0], b1 = Ws[k][j0 + 1], b2 = Ws[k][j0 + 2], b3 = Ws[k][j0 + 3];
#pragma unroll
        for (int i = 0; i < 4; i++) {
            float a = As[m0 + i][k];
            acc[i][0] = fmaf(a, b0, acc[i][0]);
            acc[i][1] = fmaf(a, b1, acc[i][1]);
            acc[i][2] = fmaf(a, b2, acc[i][2]);
            acc[i][3] = fmaf(a, b3, acc[i][3]);
        }
    }
    float bb0 = bias[j0], bb1 = bias[j0 + 1], bb2 = bias[j0 + 2], bb3 = bias[j0 + 3];
#pragma unroll
    for (int i = 0; i < 4; i++) {
        int row = block_row + m0 + i;
        if (row < n) {
            float4 o = make_float4(acc[i][0] + bb0, acc[i][1] + bb1,
                                   acc[i][2] + bb2, acc[i][3] + bb3);
            ((float4*)Cm)[row * 16 + (j0 >> 2)] = o;
        }
    }
}

// ---------------- decoder + log-softmax ----------------
__global__ void decoder_kernel(const float* __restrict__ dw,
                               const float* __restrict__ db,
                               float* __restrict__ out, int n) {
    __shared__ float Ws[HH * CC];
    __shared__ float bs[CC];
    int tid = threadIdx.x;
    for (int i = tid; i < HH * CC; i += blockDim.x) Ws[i] = dw[i];
    if (tid < CC) bs[tid] = db[tid];
    __syncthreads();
    int node = blockIdx.x * blockDim.x + tid;
    if (node >= n) return;
    float acc[CC];
#pragma unroll
    for (int c = 0; c < CC; c++) acc[c] = bs[c];
    const float4* hp = (const float4*)(g_h + node * HH);
#pragma unroll
    for (int k4 = 0; k4 < 16; k4++) {
        float4 v = hp[k4];
        int kb = k4 * 4;
#pragma unroll
        for (int c = 0; c < CC; c++)
            acc[c] += v.x * Ws[(kb + 0) * CC + c] + v.y * Ws[(kb + 1) * CC + c] +
                      v.z * Ws[(kb + 2) * CC + c] + v.w * Ws[(kb + 3) * CC + c];
    }
    float mx = acc[0];
#pragma unroll
    for (int c = 1; c < CC; c++) mx = fmaxf(mx, acc[c]);
    float s = 0.f;
#pragma unroll
    for (int c = 0; c < CC; c++) s += expf(acc[c] - mx);
    float lse = mx + logf(s);
#pragma unroll
    for (int c = 0; c < CC; c++) out[node * CC + c] = acc[c] - lse;
}

// ---------------- launch ----------------
extern "C" void kernel_launch(void* const* d_in, const int* in_sizes, int n_in,
                              void* d_out, int out_size) {
    const float* x      = (const float*)d_in[0];
    const void*  ei     = d_in[1];
    const float* enc_w  = (const float*)d_in[3];
    const float* enc_b  = (const float*)d_in[4];
    const float* proc_w = (const float*)d_in[5];
    const float* proc_b = (const float*)d_in[6];
    const float* dec_w  = (const float*)d_in[7];
    const float* dec_b  = (const float*)d_in[8];
    float* out = (float*)d_out;

    float* hptr = nullptr;
    float* aggptr = nullptr;
    cudaGetSymbolAddress((void**)&hptr, g_h);
    cudaGetSymbolAddress((void**)&aggptr, g_agg);

    const int n = NN;

    // CSR build
    zero_kernel<<<(NN + 255) / 256, 256>>>();
    detect_kernel<<<256, 256>>>((const unsigned int*)ei);
    convert_kernel<<<(EE + 255) / 256, 256>>>(ei);
    scan_phase1<<<SCAN_NBLK, SCAN_BLK>>>();
    scan_phase2<<<1, 128>>>();
    scan_phase3<<<SCAN_NBLK, SCAN_BLK>>>();
    scatter_kernel<<<(EE + 255) / 256, 256>>>();

    // encoder
    gemm64_kernel<false><<<(n + 63) / 64, 256>>>(x, nullptr, enc_w, enc_b, hptr, n);

    // 6 GIN layers
    for (int it = 0; it < 6; it++) {
        segmax_kernel<<<(NN * 32 + 255) / 256, 256>>>();
        gemm64_kernel<true><<<(n + 63) / 64, 256>>>(hptr, aggptr, proc_w, proc_b, hptr, n);
    }

    // decoder + log-softmax
    decoder_kernel<<<(n + 127) / 128, 128>>>(dec_w, dec_b, out, n);
}